// round 5
// baseline (speedup 1.0000x reference)
#include <cuda_runtime.h>
#include <math.h>

// Echo-state reservoir RNN.
//   proj = x.reshape(7168,28) @ W_in^T                (7168,128)
//   h_t  = tanh(proj_t + W_res @ h_{t-1}), h_0 = 0    (sequential over all 7168)
//   out[b] = h_{28(b+1)-1} @ W_out^T + b_out          (256,10)
//
// Parallelization: the map is contracting (spectral radius ~0.9, tanh' <= 1),
// so block b restarts the scan from h=0 at t = 28*b - WARMUP. Truncation error
// ~0.9^WARMUP ~ 6e-11 << 1e-3 tolerance. Blocks b<WARMUP/28 start at t=0 (exact).

#define H        128
#define B        256
#define T        28
#define D        28
#define TT       (B * T)       // 7168
#define WARMUP   224

// scratch: proj (7168 x 128 f32) = 3.67 MB  (static __device__: allocation-free)
__device__ float g_proj[TT * H];

// ---------------------------------------------------------------------------
// Kernel 1: proj[t][i] = sum_d x[t][d] * W_in[i][d]
// One block per batch (28 timesteps), 128 threads (one per hidden unit).
// ---------------------------------------------------------------------------
__global__ __launch_bounds__(H) void proj_kernel(const float* __restrict__ x,
                                                 const float* __restrict__ W_in) {
    __shared__ float xs[T * D];      // 784 floats: this batch's 28 input rows
    __shared__ float wi[H * D];      // 3584 floats: full W_in
    const int b = blockIdx.x;
    const int i = threadIdx.x;

    for (int idx = i; idx < H * D; idx += H) wi[idx] = W_in[idx];
    for (int idx = i; idx < T * D; idx += H) xs[idx] = x[b * (T * D) + idx];
    __syncthreads();

    for (int s = 0; s < T; s++) {
        float acc = 0.f;
        #pragma unroll
        for (int d = 0; d < D; d++) acc = fmaf(xs[s * D + d], wi[i * D + d], acc);
        g_proj[(b * T + s) * H + i] = acc;
    }
}

// ---------------------------------------------------------------------------
// Kernel 2: chunked scan. Block b produces out[b][0..9].
// Thread i keeps W_res row i entirely in registers (128 regs); h lives in
// double-buffered shared memory (float4 broadcast reads, 1 barrier/step).
// ---------------------------------------------------------------------------
__global__ __launch_bounds__(H) void scan_kernel(const float* __restrict__ W_res,
                                                 const float* __restrict__ W_out,
                                                 const float* __restrict__ b_out,
                                                 float* __restrict__ out) {
    __shared__ __align__(16) float h_s[2][H];
    const int b = blockIdx.x;
    const int i = threadIdx.x;

    // W_res row i -> registers (one-time 64KB/block read; W_res is L2-resident)
    float w[H];
    #pragma unroll
    for (int k = 0; k < H; k++) w[k] = W_res[i * H + k];

    int t0 = b * T - WARMUP;
    if (t0 < 0) t0 = 0;
    const int t_end = (b + 1) * T;   // exclusive

    h_s[0][i] = 0.f;
    __syncthreads();

    int cur = 0;
    for (int t = t0; t < t_end; t++) {
        const float pi = g_proj[t * H + i];     // issue early, consumed at the end
        float a0 = 0.f, a1 = 0.f, a2 = 0.f, a3 = 0.f;
        const float4* hv4 = reinterpret_cast<const float4*>(h_s[cur]);
        #pragma unroll
        for (int k = 0; k < H / 4; k++) {
            float4 hv = hv4[k];                 // broadcast LDS.128
            a0 = fmaf(w[4 * k + 0], hv.x, a0);
            a1 = fmaf(w[4 * k + 1], hv.y, a1);
            a2 = fmaf(w[4 * k + 2], hv.z, a2);
            a3 = fmaf(w[4 * k + 3], hv.w, a3);
        }
        const float hval = tanhf(pi + ((a0 + a1) + (a2 + a3)));
        h_s[cur ^ 1][i] = hval;
        __syncthreads();                        // readers of `cur` done; `cur^1` published
        cur ^= 1;
    }

    // epilogue: out[b][c] = h_last . W_out[c] + b_out[c]
    if (i < 10) {
        float s = b_out[i];
        #pragma unroll
        for (int k = 0; k < H; k++) s = fmaf(h_s[cur][k], W_out[i * H + k], s);
        out[b * 10 + i] = s;
    }
}

// ---------------------------------------------------------------------------
extern "C" void kernel_launch(void* const* d_in, const int* in_sizes, int n_in,
                              void* d_out, int out_size) {
    const float* x     = (const float*)d_in[0];   // (256,28,28)
    const float* W_in  = (const float*)d_in[1];   // (128,28)
    const float* W_res = (const float*)d_in[2];   // (128,128)
    const float* W_out = (const float*)d_in[3];   // (10,128)
    const float* b_out = (const float*)d_in[4];   // (10,)
    float* out = (float*)d_out;                   // (256,10)

    proj_kernel<<<B, H>>>(x, W_in);
    scan_kernel<<<B, H>>>(W_res, W_out, b_out, out);
}

// round 7
// speedup vs baseline: 1.3223x; 1.3223x over previous
#include <cuda_runtime.h>
#include <math.h>

// Echo-state reservoir RNN (chunked contracting scan).
//   proj = x.reshape(7168,28) @ W_in^T                (7168,128)
//   h_t  = tanh(proj_t + W_res @ h_{t-1}), h_0 = 0    (sequential over 7168)
//   out[b] = h_{28(b+1)-1} @ W_out^T + b_out          (256,10)
//
// Block b restarts the scan from h=0 at t = 28*b - WARMUP (contraction:
// spectral radius ~0.9). Measured truncation bound at WARMUP=224 was 3.7e-7;
// scaling by 0.9^-56 bounds WARMUP=168 error at ~1.3e-4 << 1e-3 gate.

#define H        128
#define B        256
#define T        28
#define D        28
#define TT       (B * T)       // 7168
#define WARMUP   168

__device__ float g_proj[TT * H];   // 3.67 MB scratch (static: allocation-free)

typedef unsigned long long u64;

// packed fp32x2 FMA (sm_103a FFMA2 — only reachable via PTX)
__device__ __forceinline__ u64 ffma2(u64 a, u64 b, u64 c) {
    u64 d;
    asm("fma.rn.f32x2 %0, %1, %2, %3;" : "=l"(d) : "l"(a), "l"(b), "l"(c));
    return d;
}
__device__ __forceinline__ float2 unpack2(u64 v) {
    float2 r;
    asm("mov.b64 {%0, %1}, %2;" : "=f"(r.x), "=f"(r.y) : "l"(v));
    return r;
}
__device__ __forceinline__ u64 pack2(float lo, float hi) {
    u64 v;
    asm("mov.b64 %0, {%1, %2};" : "=l"(v) : "f"(lo), "f"(hi));
    return v;
}

// fast tanh: (e^{2x}-1)/(e^{2x}+1); |x|<=20 so e^{2x} finite; MUFU-based,
// per-step abs err ~1e-7, damped by the contraction.
__device__ __forceinline__ float fast_tanh(float x) {
    x = fminf(fmaxf(x, -20.f), 20.f);
    float t = __expf(2.f * x);
    return __fdividef(t - 1.f, t + 1.f);
}

// ---------------------------------------------------------------------------
// Kernel 1: proj[t][i] = sum_d x[t][d] * W_in[i][d]
// ---------------------------------------------------------------------------
__global__ __launch_bounds__(H) void proj_kernel(const float* __restrict__ x,
                                                 const float* __restrict__ W_in) {
    __shared__ float xs[T * D];
    __shared__ float wi[H * D];
    const int b = blockIdx.x;
    const int i = threadIdx.x;

    for (int idx = i; idx < H * D; idx += H) wi[idx] = W_in[idx];
    for (int idx = i; idx < T * D; idx += H) xs[idx] = x[b * (T * D) + idx];
    __syncthreads();

    for (int s = 0; s < T; s++) {
        float acc = 0.f;
        #pragma unroll
        for (int d = 0; d < D; d++) acc = fmaf(xs[s * D + d], wi[i * D + d], acc);
        g_proj[(b * T + s) * H + i] = acc;
    }
}

// ---------------------------------------------------------------------------
// Kernel 2: chunked scan. Block b (128 threads) produces out[b][0..9].
// Thread i holds W_res row i as 64 packed f32x2 registers; h is double-
// buffered in shared, read as ulonglong2 (LDS.128 broadcast).
// ---------------------------------------------------------------------------
__global__ __launch_bounds__(H) void scan_kernel(const float* __restrict__ W_res,
                                                 const float* __restrict__ W_out,
                                                 const float* __restrict__ b_out,
                                                 float* __restrict__ out) {
    __shared__ __align__(16) float h_s[2][H];
    const int b = blockIdx.x;
    const int i = threadIdx.x;

    // W_res row i -> 64 packed pairs in registers (row is 512B-aligned)
    u64 w2[H / 2];
    const u64* wrow = reinterpret_cast<const u64*>(W_res + i * H);
    #pragma unroll
    for (int k = 0; k < H / 2; k++) w2[k] = wrow[k];

    int t0 = b * T - WARMUP;
    if (t0 < 0) t0 = 0;
    const int t_end = (b + 1) * T;   // exclusive

    h_s[0][i] = 0.f;
    __syncthreads();

    int cur = 0;
    float p_next = g_proj[t0 * H + i];          // prefetch first proj
    for (int t = t0; t < t_end; t++) {
        const float pi = p_next;
        if (t + 1 < t_end) p_next = g_proj[(t + 1) * H + i];  // pipeline next load

        u64 a0 = pack2(pi, 0.f), a1 = 0ull, a2 = 0ull, a3 = 0ull;
        const ulonglong2* hv = reinterpret_cast<const ulonglong2*>(h_s[cur]);
        #pragma unroll
        for (int k = 0; k < H / 8; k++) {       // 16 iters, 4 FFMA2 each
            ulonglong2 hA = hv[2 * k];          // h[8k..8k+3]  (LDS.128)
            ulonglong2 hB = hv[2 * k + 1];      // h[8k+4..8k+7]
            a0 = ffma2(w2[4 * k + 0], hA.x, a0);
            a1 = ffma2(w2[4 * k + 1], hA.y, a1);
            a2 = ffma2(w2[4 * k + 2], hB.x, a2);
            a3 = ffma2(w2[4 * k + 3], hB.y, a3);
        }
        float2 s0 = unpack2(a0), s1 = unpack2(a1), s2 = unpack2(a2), s3 = unpack2(a3);
        const float pre = ((s0.x + s0.y) + (s1.x + s1.y)) +
                          ((s2.x + s2.y) + (s3.x + s3.y));
        const float hval = fast_tanh(pre);
        h_s[cur ^ 1][i] = hval;
        __syncthreads();
        cur ^= 1;
    }

    // epilogue: out[b][c] = h_last . W_out[c] + b_out[c]
    if (i < 10) {
        float s = b_out[i];
        #pragma unroll
        for (int k = 0; k < H; k++) s = fmaf(h_s[cur][k], W_out[i * H + k], s);
        out[b * 10 + i] = s;
    }
}

// ---------------------------------------------------------------------------
extern "C" void kernel_launch(void* const* d_in, const int* in_sizes, int n_in,
                              void* d_out, int out_size) {
    const float* x     = (const float*)d_in[0];   // (256,28,28)
    const float* W_in  = (const float*)d_in[1];   // (128,28)
    const float* W_res = (const float*)d_in[2];   // (128,128)
    const float* W_out = (const float*)d_in[3];   // (10,128)
    const float* b_out = (const float*)d_in[4];   // (10,)
    float* out = (float*)d_out;                   // (256,10)

    proj_kernel<<<B, H>>>(x, W_in);
    scan_kernel<<<B, H>>>(W_res, W_out, b_out, out);
}